// round 15
// baseline (speedup 1.0000x reference)
#include <cuda_runtime.h>
#include <cuda_fp16.h>
#include <cstdint>

// ---------------- problem constants ----------------
#define BATCH    16
#define ZDIM     512
#define TSEQ     4096
#define NGROUPS  2
#define NENTRIES 320
#define VDIM     128
#define MROWS    (BATCH * TSEQ)          // 65536
#define NCOLS    (NGROUPS * NENTRIES)    // 640
#define KDIM     ZDIM                    // 512
#define LOGITS_ELEMS ((size_t)MROWS * NCOLS)

// ---------------- GEMM tiling ----------------
#define M_TILE   128
#define N_TILE   128
#define KC       32
#define NCHUNK   (KDIM / KC)             // 16
#define THREADS  256
#define NHALVES  10

// SMEM: unified 4-stage ring; each stage = A 8KB + B 8KB
#define STAGE      16384
#define SMEM_BYTES (4 * STAGE)           // 64 KB -> 2 CTAs/SM

// refine gating threshold: ~24 sigma of approx-logit comparison error
#define GAP_THRESH 8e-3f

// ---------------- device scratch ----------------
__device__ __half g_whi[NCOLS * KDIM];
// x fp16, tile-major: [MROWS/128][KDIM][128]
__device__ __half g_xh[(size_t)MROWS * KDIM];
__device__ float4 g_part2[(size_t)NHALVES * MROWS];

__device__ __forceinline__ uint32_t smem_u32(const void* p) {
    uint32_t a;
    asm("{ .reg .u64 t; cvta.to.shared.u64 t, %1; cvt.u32.u64 %0, t; }" : "=r"(a) : "l"(p));
    return a;
}

#define CP_ASYNC16(dst, src) \
    asm volatile("cp.async.cg.shared.global [%0], [%1], 16;" :: "r"(dst), "l"(src))
#define CP_COMMIT() asm volatile("cp.async.commit_group;")
#define CP_WAIT2()  asm volatile("cp.async.wait_group 2;")

__device__ __forceinline__ void ldm_x4(uint32_t addr, uint32_t& r0, uint32_t& r1,
                                       uint32_t& r2, uint32_t& r3) {
    asm volatile("ldmatrix.sync.aligned.m8n8.x4.shared.b16 {%0,%1,%2,%3}, [%4];"
                 : "=r"(r0), "=r"(r1), "=r"(r2), "=r"(r3) : "r"(addr));
}
__device__ __forceinline__ void ldm_x4t(uint32_t addr, uint32_t& r0, uint32_t& r1,
                                        uint32_t& r2, uint32_t& r3) {
    asm volatile("ldmatrix.sync.aligned.m8n8.x4.trans.shared.b16 {%0,%1,%2,%3}, [%4];"
                 : "=r"(r0), "=r"(r1), "=r"(r2), "=r"(r3) : "r"(addr));
}

__device__ __forceinline__ void mma_f16(float& c0, float& c1, float& c2, float& c3,
                                        uint32_t a0, uint32_t a1, uint32_t a2, uint32_t a3,
                                        uint32_t b0, uint32_t b1) {
    asm volatile("mma.sync.aligned.m16n8k16.row.col.f32.f16.f16.f32 "
                 "{%0,%1,%2,%3}, {%4,%5,%6,%7}, {%8,%9}, {%0,%1,%2,%3};"
                 : "+f"(c0), "+f"(c1), "+f"(c2), "+f"(c3)
                 : "r"(a0), "r"(a1), "r"(a2), "r"(a3), "r"(b0), "r"(b1));
}

__device__ __forceinline__ uint32_t sw_off_b(int row, int c16) {
    return (uint32_t)(row * 64 + ((c16 ^ ((row >> 1) & 3)) << 4));
}
__device__ __forceinline__ uint32_t sw_off_a(int krow, int munit) {
    return (uint32_t)(krow * 256 + ((munit ^ (krow & 7)) << 4));
}

// ============================================================
// Pre-pass 1: proj_w fp32 -> fp16
// ============================================================
__global__ __launch_bounds__(1024)
void split_w_kernel(const float* __restrict__ w) {
    int idx = blockIdx.x * blockDim.x + threadIdx.x;
    if (idx < NCOLS * KDIM)
        g_whi[idx] = __float2half_rn(w[idx]);
}

// ============================================================
// Pre-pass 2: x fp32 (B,Z,T) -> fp16 tile-major [m/128][k][m%128]
// t is the fast axis on BOTH sides -> fully coalesced copy.
// ============================================================
__global__ __launch_bounds__(1024)
void split_x_kernel(const float* __restrict__ x) {
    size_t idx4 = (size_t)blockIdx.x * 1024 + threadIdx.x;   // float4 index
    size_t e = idx4 * 4;
    int t = (int)(e & 4095);
    int k = (int)((e >> 12) & 511);
    int b = (int)(e >> 21);
    float4 v = ((const float4*)x)[idx4];
    int m = b * TSEQ + t;
    size_t off = ((size_t)(m >> 7) * KDIM + k) * 128 + (m & 127);
    __half2 h0 = __floats2half2_rn(v.x, v.y);
    __half2 h1 = __floats2half2_rn(v.z, v.w);
    *(uint2*)(g_xh + off) = make_uint2(*(uint32_t*)&h0, *(uint32_t*)&h1);
}

// ============================================================
// GEMM (pure fp16, fp32 accumulate): A and B both via cp.async,
// software-pipelined fragment loads, fused epilogue + top-2 argmax.
// ============================================================
__global__ __launch_bounds__(THREADS, 2)
void pq_gemm_kernel(const float* __restrict__ bias,
                    const float* __restrict__ gumbel,  // (BT, 640)
                    float* __restrict__ logits)
{
    extern __shared__ char smem[];
    const uint32_t sbase = smem_u32(smem);
    const int tid  = threadIdx.x;
    const int wid  = tid >> 5;
    const int lane = tid & 31;
    const int m0   = blockIdx.y * M_TILE;
    const int n0   = blockIdx.x * N_TILE;

    const int mwarp = wid >> 1;
    const int nwarp = wid & 1;

    float acc[2][8][4];
#pragma unroll
    for (int mi = 0; mi < 2; mi++)
#pragma unroll
        for (int nf = 0; nf < 8; nf++)
#pragma unroll
            for (int r = 0; r < 4; r++) acc[mi][nf][r] = 0.0f;

    // A cp.async mapping: row = tid>>3 (0..31), units (tid&7), (tid&7)+8
    const int arow_l = tid >> 3;
    const int au0    = tid & 7;
    // B cp.async mapping: row = tid>>1 (0..127), units (tid&1)*2 + {0,1}
    const int lrow = tid >> 1;
    const int lcb  = (tid & 1) * 2;

    const __half* xtile = g_xh + (size_t)blockIdx.y * KDIM * 128;

    auto issue_ab = [&](int c) {
        const uint32_t st = sbase + (uint32_t)(c & 3) * STAGE;
        // A: 32 k-rows x 256B
        const __half* ga = xtile + (size_t)(c * KC + arow_l) * 128;
        CP_ASYNC16(st + sw_off_a(arow_l, au0),     ga + au0 * 8);
        CP_ASYNC16(st + sw_off_a(arow_l, au0 + 8), ga + (au0 + 8) * 8);
        // B: 128 n-rows x 64B
        const int kk = c * KC;
#pragma unroll
        for (int u = 0; u < 2; u++) {
            int c16 = lcb + u;
            const __half* gb = g_whi + (size_t)(n0 + lrow) * KDIM + kk + c16 * 8;
            CP_ASYNC16(st + 8192 + sw_off_b(lrow, c16), gb);
        }
        CP_COMMIT();
    };

    issue_ab(0); issue_ab(1); issue_ab(2);

    const int grp = lane >> 3;
    const int kq  = lane & 7;
    const int brow = nwarp * 64 + (lane & 7) + ((lane >> 4) << 3);
    const int mu0  = ((mwarp * 32) >> 3) + (grp & 1);
    const int mu1  = ((mwarp * 32 + 16) >> 3) + (grp & 1);

    for (int c = 0; c < NCHUNK; ++c) {
        CP_WAIT2();
        __syncthreads();
        if (c + 3 < NCHUNK) issue_ab(c + 3);
        else CP_COMMIT();

        const uint32_t abase = sbase + (uint32_t)(c & 3) * STAGE;
        const uint32_t bbase = abase + 8192;

        // A-fragment double buffer across the 2 ks steps
        uint32_t ah[2][2][4];
        {
            const int arow0 = ((grp >> 1) << 3) + kq;
            ldm_x4t(abase + sw_off_a(arow0, mu0), ah[0][0][0], ah[0][0][1], ah[0][0][2], ah[0][0][3]);
            ldm_x4t(abase + sw_off_a(arow0, mu1), ah[0][1][0], ah[0][1][1], ah[0][1][2], ah[0][1][3]);
        }

#pragma unroll
        for (int ks = 0; ks < 2; ks++) {
            const int bc16 = ks * 2 + ((lane >> 3) & 1);

            uint32_t bb[2][4];
            ldm_x4(bbase + sw_off_b(brow, bc16), bb[0][0], bb[0][1], bb[0][2], bb[0][3]);
#pragma unroll
            for (int j = 0; j < 4; j++) {
                if (j < 3) {
                    ldm_x4(bbase + sw_off_b(brow + (j + 1) * 16, bc16),
                           bb[(j + 1) & 1][0], bb[(j + 1) & 1][1],
                           bb[(j + 1) & 1][2], bb[(j + 1) & 1][3]);
                } else if (ks == 0) {
                    const int arow1 = 16 + ((grp >> 1) << 3) + kq;
                    ldm_x4t(abase + sw_off_a(arow1, mu0), ah[1][0][0], ah[1][0][1], ah[1][0][2], ah[1][0][3]);
                    ldm_x4t(abase + sw_off_a(arow1, mu1), ah[1][1][0], ah[1][1][1], ah[1][1][2], ah[1][1][3]);
                }
#pragma unroll
                for (int mi = 0; mi < 2; mi++) {
#pragma unroll
                    for (int t = 0; t < 2; t++) {
                        int nf = j * 2 + t;
                        int h  = t * 2;
                        mma_f16(acc[mi][nf][0], acc[mi][nf][1], acc[mi][nf][2], acc[mi][nf][3],
                                ah[ks][mi][0], ah[ks][mi][1], ah[ks][mi][2], ah[ks][mi][3],
                                bb[j & 1][h], bb[j & 1][h + 1]);
                    }
                }
            }
        }
    }

    // ---- fused epilogue: bias + logits store + TOP-2 perturbed argmax ----
    float v1[4], v2[4];
    int   i1[4], i2[4];
#pragma unroll
    for (int rp = 0; rp < 4; rp++) { v1[rp] = -3.4e38f; v2[rp] = -3.4e38f; i1[rp] = 0; i2[rp] = 1; }

#define UPD2(rp, p, c) do { \
    if ((p) > v1[rp]) { v2[rp] = v1[rp]; i2[rp] = i1[rp]; v1[rp] = (p); i1[rp] = (c); } \
    else if ((p) > v2[rp]) { v2[rp] = (p); i2[rp] = (c); } } while (0)

#pragma unroll
    for (int nf = 0; nf < 8; nf++) {
        int col = n0 + nwarp * 64 + nf * 8 + (lane & 3) * 2;
        float b0 = __ldg(bias + col);
        float b1 = __ldg(bias + col + 1);
#pragma unroll
        for (int mi = 0; mi < 2; mi++) {
            int row = m0 + mwarp * 32 + mi * 16 + (lane >> 2);
            float v00 = acc[mi][nf][0] + b0, v01 = acc[mi][nf][1] + b1;
            float v10 = acc[mi][nf][2] + b0, v11 = acc[mi][nf][3] + b1;
            *(float2*)(logits + (size_t)row * NCOLS + col)       = make_float2(v00, v01);
            *(float2*)(logits + (size_t)(row + 8) * NCOLS + col) = make_float2(v10, v11);
            float2 g0 = *(const float2*)(gumbel + (size_t)row * NCOLS + col);
            float2 g1 = *(const float2*)(gumbel + (size_t)(row + 8) * NCOLS + col);
            int rp0 = mi * 2, rp1 = mi * 2 + 1;
            float p;
            p = v00 + g0.x; UPD2(rp0, p, col);
            p = v01 + g0.y; UPD2(rp0, p, col + 1);
            p = v10 + g1.x; UPD2(rp1, p, col);
            p = v11 + g1.y; UPD2(rp1, p, col + 1);
        }
    }

    // 4-lane top-2 merge (tie -> lower index)
#pragma unroll
    for (int rp = 0; rp < 4; rp++) {
#pragma unroll
        for (int off = 1; off <= 2; off <<= 1) {
            float ov1 = __shfl_xor_sync(0xffffffffu, v1[rp], off);
            int   oi1 = __shfl_xor_sync(0xffffffffu, i1[rp], off);
            float ov2 = __shfl_xor_sync(0xffffffffu, v2[rp], off);
            int   oi2 = __shfl_xor_sync(0xffffffffu, i2[rp], off);
            bool o_first = (ov1 > v1[rp]) || (ov1 == v1[rp] && oi1 < i1[rp]);
            if (o_first) {
                float nv2; int ni2;
                if (v1[rp] > ov2 || (v1[rp] == ov2 && i1[rp] < oi2)) { nv2 = v1[rp]; ni2 = i1[rp]; }
                else { nv2 = ov2; ni2 = oi2; }
                v1[rp] = ov1; i1[rp] = oi1; v2[rp] = nv2; i2[rp] = ni2;
            } else {
                if (ov1 > v2[rp] || (ov1 == v2[rp] && oi1 < i2[rp])) { v2[rp] = ov1; i2[rp] = oi1; }
            }
        }
    }
    if ((lane & 3) == 0) {
        const int h = blockIdx.x * 2 + nwarp;
#pragma unroll
        for (int rp = 0; rp < 4; rp++) {
            int row = m0 + mwarp * 32 + (rp >> 1) * 16 + (rp & 1) * 8 + (lane >> 2);
            g_part2[(size_t)h * MROWS + row] =
                make_float4(v1[rp], __int_as_float(i1[rp]), v2[rp], __int_as_float(i2[rp]));
        }
    }
#undef UPD2
}

// ============================================================
// Gap-gated refine + gather. One warp per (bt, g) group.
// ============================================================
__global__ __launch_bounds__(256)
void pq_refine_kernel(const float* __restrict__ x,
                      const float* __restrict__ w,
                      const float* __restrict__ bias,
                      const float* __restrict__ gumbel,
                      const float* __restrict__ cv,
                      float* __restrict__ q)
{
    const int warp = (blockIdx.x * blockDim.x + threadIdx.x) >> 5;
    const int lane = threadIdx.x & 31;
    if (warp >= MROWS * NGROUPS) return;

    const int bt = warp >> 1;
    const int g  = warp & 1;

    float bv1 = -3.4e38f, bv2 = -3.4e38f;
    int   bc1 = 0, bc2 = 1;
#pragma unroll
    for (int hq = 0; hq < 5; hq++) {
        float4 P = __ldg(&g_part2[(size_t)(g * 5 + hq) * MROWS + bt]);
        float pv; int pc;
        pv = P.x; pc = __float_as_int(P.y);
        if (pv > bv1 || (pv == bv1 && pc < bc1)) { bv2 = bv1; bc2 = bc1; bv1 = pv; bc1 = pc; }
        else if (pv > bv2 || (pv == bv2 && pc < bc2)) { bv2 = pv; bc2 = pc; }
        pv = P.z; pc = __float_as_int(P.w);
        if (pv > bv1 || (pv == bv1 && pc < bc1)) { bv2 = bv1; bc2 = bc1; bv1 = pv; bc1 = pc; }
        else if (pv > bv2 || (pv == bv2 && pc < bc2)) { bv2 = pv; bc2 = pc; }
    }

    int wcol = bc1;
    if (bv1 - bv2 <= GAP_THRESH) {
        const int b = bt >> 12;
        const int t = bt & 4095;
        const float* xb = x + (size_t)b * KDIM * TSEQ + t;
        const float* w0 = w + (size_t)bc1 * KDIM;
        const float* w1 = w + (size_t)bc2 * KDIM;
        float s0 = 0.0f, s1 = 0.0f;
#pragma unroll
        for (int s = 0; s < 16; s++) {
            int k = lane + 32 * s;
            float xv = __ldg(xb + (size_t)k * TSEQ);
            s0 = fmaf(xv, __ldg(w0 + k), s0);
            s1 = fmaf(xv, __ldg(w1 + k), s1);
        }
#pragma unroll
        for (int off = 16; off > 0; off >>= 1) {
            s0 += __shfl_xor_sync(0xffffffffu, s0, off);
            s1 += __shfl_xor_sync(0xffffffffu, s1, off);
        }
        float p0 = s0 + __ldg(bias + bc1) + __ldg(gumbel + (size_t)bt * NCOLS + bc1);
        float p1 = s1 + __ldg(bias + bc2) + __ldg(gumbel + (size_t)bt * NCOLS + bc2);
        wcol = (p1 > p0 || (p1 == p0 && bc2 < bc1)) ? bc2 : bc1;
    }

    const float4* src = (const float4*)(cv + (size_t)wcol * VDIM);
    float4*       dst = (float4*)(q + (size_t)bt * (NGROUPS * VDIM) + (size_t)g * VDIM);
    dst[lane] = __ldg(src + lane);
}

// ============================================================
extern "C" void kernel_launch(void* const* d_in, const int* in_sizes, int n_in,
                              void* d_out, int out_size) {
    const float* x      = (const float*)d_in[0];
    const float* gumbel = (const float*)d_in[1];
    const float* proj_w = (const float*)d_in[2];
    const float* proj_b = (const float*)d_in[3];
    const float* cv     = (const float*)d_in[4];

    float* out    = (float*)d_out;
    float* logits = out;
    float* q      = out + LOGITS_ELEMS;

    split_w_kernel<<<(NCOLS * KDIM + 1023) / 1024, 1024>>>(proj_w);
    split_x_kernel<<<(MROWS * KDIM / 4 + 1023) / 1024, 1024>>>(x);

    cudaFuncSetAttribute(pq_gemm_kernel,
                         cudaFuncAttributeMaxDynamicSharedMemorySize, SMEM_BYTES);
    pq_gemm_kernel<<<dim3(NCOLS / N_TILE, MROWS / M_TILE), THREADS, SMEM_BYTES>>>(
        proj_b, gumbel, logits);

    int blocks = (MROWS * NGROUPS * 32 + 255) / 256;
    pq_refine_kernel<<<blocks, 256>>>(x, proj_w, proj_b, gumbel, cv, q);
}

// round 16
// speedup vs baseline: 1.1110x; 1.1110x over previous
#include <cuda_runtime.h>
#include <cuda_fp16.h>
#include <cstdint>

// ---------------- problem constants ----------------
#define BATCH    16
#define ZDIM     512
#define TSEQ     4096
#define NGROUPS  2
#define NENTRIES 320
#define VDIM     128
#define MROWS    (BATCH * TSEQ)          // 65536
#define NCOLS    (NGROUPS * NENTRIES)    // 640
#define KDIM     ZDIM                    // 512
#define LOGITS_ELEMS ((size_t)MROWS * NCOLS)

// ---------------- GEMM tiling (R13 best config) ----------------
#define M_TILE   128
#define N_TILE   128
#define KC       32
#define NCHUNK   (KDIM / KC)             // 16
#define THREADS  256
#define NHALVES  10

// SMEM: A fp16 double buffer + B fp16 4-stage ring
#define ABF_SLOT   8192
#define OFF_ABF    0
#define OFF_B      16384
#define BSTAGE     8192
#define SMEM_BYTES (OFF_B + 4 * BSTAGE)  // 48 KB

// refine gating threshold: ~24 sigma of approx-logit comparison error
#define GAP_THRESH 8e-3f
#define RGROUPS    256                   // groups per refine block

// ---------------- device scratch ----------------
__device__ __half g_whi[NCOLS * KDIM];
__device__ float4 g_part2[(size_t)NHALVES * MROWS];

__device__ __forceinline__ uint32_t smem_u32(const void* p) {
    uint32_t a;
    asm("{ .reg .u64 t; cvta.to.shared.u64 t, %1; cvt.u32.u64 %0, t; }" : "=r"(a) : "l"(p));
    return a;
}

#define CP_ASYNC16(dst, src) \
    asm volatile("cp.async.cg.shared.global [%0], [%1], 16;" :: "r"(dst), "l"(src))
#define CP_COMMIT() asm volatile("cp.async.commit_group;")
#define CP_WAIT2()  asm volatile("cp.async.wait_group 2;")

__device__ __forceinline__ void ldm_x4(uint32_t addr, uint32_t& r0, uint32_t& r1,
                                       uint32_t& r2, uint32_t& r3) {
    asm volatile("ldmatrix.sync.aligned.m8n8.x4.shared.b16 {%0,%1,%2,%3}, [%4];"
                 : "=r"(r0), "=r"(r1), "=r"(r2), "=r"(r3) : "r"(addr));
}
__device__ __forceinline__ void ldm_x4t(uint32_t addr, uint32_t& r0, uint32_t& r1,
                                        uint32_t& r2, uint32_t& r3) {
    asm volatile("ldmatrix.sync.aligned.m8n8.x4.trans.shared.b16 {%0,%1,%2,%3}, [%4];"
                 : "=r"(r0), "=r"(r1), "=r"(r2), "=r"(r3) : "r"(addr));
}

__device__ __forceinline__ void mma_f16(float& c0, float& c1, float& c2, float& c3,
                                        uint32_t a0, uint32_t a1, uint32_t a2, uint32_t a3,
                                        uint32_t b0, uint32_t b1) {
    asm volatile("mma.sync.aligned.m16n8k16.row.col.f32.f16.f16.f32 "
                 "{%0,%1,%2,%3}, {%4,%5,%6,%7}, {%8,%9}, {%0,%1,%2,%3};"
                 : "+f"(c0), "+f"(c1), "+f"(c2), "+f"(c3)
                 : "r"(a0), "r"(a1), "r"(a2), "r"(a3), "r"(b0), "r"(b1));
}

__device__ __forceinline__ uint32_t sw_off_b(int row, int c16) {
    return (uint32_t)(row * 64 + ((c16 ^ ((row >> 1) & 3)) << 4));
}
__device__ __forceinline__ uint32_t sw_off_a(int krow, int munit) {
    return (uint32_t)(krow * 256 + ((munit ^ (krow & 7)) << 4));
}

// ============================================================
// Pre-pass: convert proj_w fp32 -> fp16
// ============================================================
__global__ __launch_bounds__(1024)
void split_w_kernel(const float* __restrict__ w) {
    int idx = blockIdx.x * blockDim.x + threadIdx.x;
    if (idx < NCOLS * KDIM)
        g_whi[idx] = __float2half_rn(w[idx]);
}

// ============================================================
// GEMM (pure fp16, fp32 accumulate), in-kernel A convert,
// fused logits write + top-2 perturbed partial argmax.
// (exact R13 structure — the 237.5us configuration)
// ============================================================
__global__ __launch_bounds__(THREADS, 2)
void pq_gemm_kernel(const float* __restrict__ x,      // (B, Z, T)
                    const float* __restrict__ bias,
                    const float* __restrict__ gumbel,  // (BT, 640)
                    float* __restrict__ logits)
{
    extern __shared__ char smem[];
    const uint32_t sbase = smem_u32(smem);
    const int tid  = threadIdx.x;
    const int wid  = tid >> 5;
    const int lane = tid & 31;
    const int m0   = blockIdx.y * M_TILE;
    const int n0   = blockIdx.x * N_TILE;
    const int b    = m0 >> 12;
    const int t0   = m0 & 4095;

    const int mwarp = wid >> 1;
    const int nwarp = wid & 1;

    float acc[2][8][4];
#pragma unroll
    for (int mi = 0; mi < 2; mi++)
#pragma unroll
        for (int nf = 0; nf < 8; nf++)
#pragma unroll
            for (int r = 0; r < 4; r++) acc[mi][nf][r] = 0.0f;

    const float* xrow0 = x + ((size_t)b * KDIM + (size_t)(wid * 4)) * TSEQ + t0 + lane * 4;
    float4 areg[4];

    const int lrow = tid >> 1;
    const int lcb  = (tid & 1) * 2;

    auto issue_b = [&](int c) {
        const int kk = c * KC;
        const uint32_t st = sbase + OFF_B + (uint32_t)(c & 3) * BSTAGE;
#pragma unroll
        for (int u = 0; u < 2; u++) {
            int c16 = lcb + u;
            uint32_t so = sw_off_b(lrow, c16);
            const __half* gh = g_whi + (size_t)(n0 + lrow) * KDIM + kk + c16 * 8;
            CP_ASYNC16(st + so, gh);
        }
        CP_COMMIT();
    };

    auto lda = [&](int c) {
#pragma unroll
        for (int i = 0; i < 4; i++)
            areg[i] = *(const float4*)(xrow0 + ((size_t)(c * KC) + i) * TSEQ);
    };

    lda(0);
    issue_b(0); issue_b(1); issue_b(2);

    for (int c = 0; c < NCHUNK; ++c) {
        // ---- convert A regs -> fp16 smem ----
        {
            char* abuf = smem + OFF_ABF + (c & 1) * ABF_SLOT;
#pragma unroll
            for (int i = 0; i < 4; i++) {
                float4 v = areg[i];
                int k = wid * 4 + i;
                uint32_t off = (uint32_t)(k * 256) +
                               ((((uint32_t)(lane >> 1)) ^ (uint32_t)(k & 7)) << 4) +
                               (uint32_t)((lane & 1) * 8);
                __half2 hp0 = __floats2half2_rn(v.x, v.y);
                __half2 hp1 = __floats2half2_rn(v.z, v.w);
                ((uint2*)(abuf + off))[0] = make_uint2(*(uint32_t*)&hp0, *(uint32_t*)&hp1);
            }
        }
        if (c + 1 < NCHUNK) lda(c + 1);

        CP_WAIT2();
        __syncthreads();
        if (c + 3 < NCHUNK) issue_b(c + 3);
        else CP_COMMIT();

        const uint32_t abase = sbase + OFF_ABF + (uint32_t)(c & 1) * ABF_SLOT;
        const uint32_t bbase = sbase + OFF_B + (uint32_t)(c & 3) * BSTAGE;

        const int grp = lane >> 3;
        const int kq  = lane & 7;
        const int brow = nwarp * 64 + (lane & 7) + ((lane >> 4) << 3);

#pragma unroll
        for (int ks = 0; ks < 2; ks++) {
            const int arow = ks * 16 + ((grp >> 1) << 3) + kq;
            const int bc16 = ks * 2 + ((lane >> 3) & 1);

            uint32_t ah[2][4];
#pragma unroll
            for (int mi = 0; mi < 2; mi++) {
                int munit = ((mwarp * 32 + mi * 16) >> 3) + (grp & 1);
                ldm_x4t(abase + sw_off_a(arow, munit), ah[mi][0], ah[mi][1], ah[mi][2], ah[mi][3]);
            }

#pragma unroll
            for (int j = 0; j < 4; j++) {
                uint32_t bh[4];
                ldm_x4(bbase + sw_off_b(brow + j * 16, bc16), bh[0], bh[1], bh[2], bh[3]);
#pragma unroll
                for (int mi = 0; mi < 2; mi++) {
#pragma unroll
                    for (int t = 0; t < 2; t++) {
                        int nf = j * 2 + t;
                        int h  = t * 2;
                        mma_f16(acc[mi][nf][0], acc[mi][nf][1], acc[mi][nf][2], acc[mi][nf][3],
                                ah[mi][0], ah[mi][1], ah[mi][2], ah[mi][3], bh[h], bh[h + 1]);
                    }
                }
            }
        }
    }

    // ---- fused epilogue: bias + logits store + TOP-2 perturbed argmax ----
    float v1[4], v2[4];
    int   i1[4], i2[4];
#pragma unroll
    for (int rp = 0; rp < 4; rp++) { v1[rp] = -3.4e38f; v2[rp] = -3.4e38f; i1[rp] = 0; i2[rp] = 1; }

#define UPD2(rp, p, c) do { \
    if ((p) > v1[rp]) { v2[rp] = v1[rp]; i2[rp] = i1[rp]; v1[rp] = (p); i1[rp] = (c); } \
    else if ((p) > v2[rp]) { v2[rp] = (p); i2[rp] = (c); } } while (0)

#pragma unroll
    for (int nf = 0; nf < 8; nf++) {
        int col = n0 + nwarp * 64 + nf * 8 + (lane & 3) * 2;
        float b0 = __ldg(bias + col);
        float b1 = __ldg(bias + col + 1);
#pragma unroll
        for (int mi = 0; mi < 2; mi++) {
            int row = m0 + mwarp * 32 + mi * 16 + (lane >> 2);
            float v00 = acc[mi][nf][0] + b0, v01 = acc[mi][nf][1] + b1;
            float v10 = acc[mi][nf][2] + b0, v11 = acc[mi][nf][3] + b1;
            *(float2*)(logits + (size_t)row * NCOLS + col)       = make_float2(v00, v01);
            *(float2*)(logits + (size_t)(row + 8) * NCOLS + col) = make_float2(v10, v11);
            float2 g0 = *(const float2*)(gumbel + (size_t)row * NCOLS + col);
            float2 g1 = *(const float2*)(gumbel + (size_t)(row + 8) * NCOLS + col);
            int rp0 = mi * 2, rp1 = mi * 2 + 1;
            float p;
            p = v00 + g0.x; UPD2(rp0, p, col);
            p = v01 + g0.y; UPD2(rp0, p, col + 1);
            p = v10 + g1.x; UPD2(rp1, p, col);
            p = v11 + g1.y; UPD2(rp1, p, col + 1);
        }
    }

    // 4-lane top-2 merge (tie -> lower index)
#pragma unroll
    for (int rp = 0; rp < 4; rp++) {
#pragma unroll
        for (int off = 1; off <= 2; off <<= 1) {
            float ov1 = __shfl_xor_sync(0xffffffffu, v1[rp], off);
            int   oi1 = __shfl_xor_sync(0xffffffffu, i1[rp], off);
            float ov2 = __shfl_xor_sync(0xffffffffu, v2[rp], off);
            int   oi2 = __shfl_xor_sync(0xffffffffu, i2[rp], off);
            bool o_first = (ov1 > v1[rp]) || (ov1 == v1[rp] && oi1 < i1[rp]);
            if (o_first) {
                float nv2; int ni2;
                if (v1[rp] > ov2 || (v1[rp] == ov2 && i1[rp] < oi2)) { nv2 = v1[rp]; ni2 = i1[rp]; }
                else { nv2 = ov2; ni2 = oi2; }
                v1[rp] = ov1; i1[rp] = oi1; v2[rp] = nv2; i2[rp] = ni2;
            } else {
                if (ov1 > v2[rp] || (ov1 == v2[rp] && oi1 < i2[rp])) { v2[rp] = ov1; i2[rp] = oi1; }
            }
        }
    }
    if ((lane & 3) == 0) {
        const int h = blockIdx.x * 2 + nwarp;
#pragma unroll
        for (int rp = 0; rp < 4; rp++) {
            int row = m0 + mwarp * 32 + (rp >> 1) * 16 + (rp & 1) * 8 + (lane >> 2);
            g_part2[(size_t)h * MROWS + row] =
                make_float4(v1[rp], __int_as_float(i1[rp]), v2[rp], __int_as_float(i2[rp]));
        }
    }
#undef UPD2
}

// ============================================================
// Refine v2: 3 phases per block of 256 groups.
//   P1 thread-per-group top-2 select + gap gate (32x less ALU)
//   P2 warp-cooperative exact fp32 recompute for queued groups
//   P3 warp-per-group codevector gather
// ============================================================
__global__ __launch_bounds__(256)
void pq_refine_kernel(const float* __restrict__ x,
                      const float* __restrict__ w,
                      const float* __restrict__ bias,
                      const float* __restrict__ gumbel,
                      const float* __restrict__ cv,
                      float* __restrict__ q)
{
    __shared__ int s_wcol[RGROUPS];
    __shared__ int s_slow[RGROUPS];
    __shared__ int s_nslow;

    const int tid = threadIdx.x;
    const int gbase = blockIdx.x * RGROUPS;
    if (tid == 0) s_nslow = 0;
    __syncthreads();

    // ---- Phase 1: per-thread top-2 selection over 10 candidates ----
    {
        const int gidx = gbase + tid;
        const int bt = gidx >> 1;
        const int g  = gidx & 1;

        float bv1 = -3.4e38f, bv2 = -3.4e38f;
        int   bc1 = 0, bc2 = 1;
#pragma unroll
        for (int hq = 0; hq < 5; hq++) {
            float4 P = __ldg(&g_part2[(size_t)(g * 5 + hq) * MROWS + bt]);
            float pv; int pc;
            pv = P.x; pc = __float_as_int(P.y);
            if (pv > bv1 || (pv == bv1 && pc < bc1)) { bv2 = bv1; bc2 = bc1; bv1 = pv; bc1 = pc; }
            else if (pv > bv2 || (pv == bv2 && pc < bc2)) { bv2 = pv; bc2 = pc; }
            pv = P.z; pc = __float_as_int(P.w);
            if (pv > bv1 || (pv == bv1 && pc < bc1)) { bv2 = bv1; bc2 = bc1; bv1 = pv; bc1 = pc; }
            else if (pv > bv2 || (pv == bv2 && pc < bc2)) { bv2 = pv; bc2 = pc; }
        }
        s_wcol[tid] = bc1;
        if (bv1 - bv2 <= GAP_THRESH) {
            int slot = atomicAdd(&s_nslow, 1);
            s_slow[slot] = tid | (bc1 << 8) | (bc2 << 18);
        }
    }
    __syncthreads();

    const int wid  = tid >> 5;
    const int lane = tid & 31;
    const int nslow = s_nslow;

    // ---- Phase 2: warp-cooperative exact recompute for queued groups ----
    for (int i = wid; i < nslow; i += 8) {
        int e = s_slow[i];
        int ltid = e & 255;
        int bc1  = (e >> 8) & 1023;
        int bc2  = (e >> 18) & 1023;
        int gidx = gbase + ltid;
        int bt = gidx >> 1;
        const int b = bt >> 12;
        const int t = bt & 4095;
        const float* xb = x + (size_t)b * KDIM * TSEQ + t;
        const float* w0 = w + (size_t)bc1 * KDIM;
        const float* w1 = w + (size_t)bc2 * KDIM;
        float s0 = 0.0f, s1 = 0.0f;
#pragma unroll
        for (int s = 0; s < 16; s++) {
            int k = lane + 32 * s;
            float xv = __ldg(xb + (size_t)k * TSEQ);
            s0 = fmaf(xv, __ldg(w0 + k), s0);
            s1 = fmaf(xv, __ldg(w1 + k), s1);
        }
#pragma unroll
        for (int off = 16; off > 0; off >>= 1) {
            s0 += __shfl_xor_sync(0xffffffffu, s0, off);
            s1 += __shfl_xor_sync(0xffffffffu, s1, off);
        }
        float p0 = s0 + __ldg(bias + bc1) + __ldg(gumbel + (size_t)bt * NCOLS + bc1);
        float p1 = s1 + __ldg(bias + bc2) + __ldg(gumbel + (size_t)bt * NCOLS + bc2);
        int wcol = (p1 > p0 || (p1 == p0 && bc2 < bc1)) ? bc2 : bc1;
        if (lane == 0) s_wcol[ltid] = wcol;
    }
    __syncthreads();

    // ---- Phase 3: warp-per-group codevector gather ----
    for (int i = wid; i < RGROUPS; i += 8) {
        int gidx = gbase + i;
        int bt = gidx >> 1;
        int g  = gidx & 1;
        int wcol = s_wcol[i];
        const float4* src = (const float4*)(cv + (size_t)wcol * VDIM);
        float4*       dst = (float4*)(q + (size_t)bt * (NGROUPS * VDIM) + (size_t)g * VDIM);
        dst[lane] = __ldg(src + lane);
    }
}

// ============================================================
extern "C" void kernel_launch(void* const* d_in, const int* in_sizes, int n_in,
                              void* d_out, int out_size) {
    const float* x      = (const float*)d_in[0];
    const float* gumbel = (const float*)d_in[1];
    const float* proj_w = (const float*)d_in[2];
    const float* proj_b = (const float*)d_in[3];
    const float* cv     = (const float*)d_in[4];

    float* out    = (float*)d_out;
    float* logits = out;
    float* q      = out + LOGITS_ELEMS;

    split_w_kernel<<<(NCOLS * KDIM + 1023) / 1024, 1024>>>(proj_w);

    cudaFuncSetAttribute(pq_gemm_kernel,
                         cudaFuncAttributeMaxDynamicSharedMemorySize, SMEM_BYTES);
    pq_gemm_kernel<<<dim3(NCOLS / N_TILE, MROWS / M_TILE), THREADS, SMEM_BYTES>>>(
        x, proj_b, gumbel, logits);

    pq_refine_kernel<<<MROWS * NGROUPS / RGROUPS, 256>>>(x, proj_w, proj_b, gumbel, cv, q);
}